// round 14
// baseline (speedup 1.0000x reference)
#include <cuda_runtime.h>

#define NN 100000
#define EE 3200000
#define ET (EE + NN)

// ---------------- scratch (device globals; no runtime allocation) ----------
__device__ int g_is64;
__device__ __align__(16) int2   g_edge[ET];        // decoded (src,dst) incl self-loops
__device__ __align__(16) float  g_h1[NN * 32];     // layer1 transformed features
__device__ __align__(16) float4 g_a1[NN];          // (a_src h0, a_src h1, a_dst h0, a_dst h1)
__device__ __align__(8)  float2 g_s1[NN];          // segment expsum per head
__device__ __align__(16) float  g_out1[NN * 32];   // layer1 aggregate (unnormalized)
__device__ __align__(16) float  g_h2[NN * 40];
__device__ __align__(8)  float2 g_a2[NN];          // (a_src, a_dst)
__device__ float g_s2[NN];

// ---------------- helpers ---------------------------------------------------
__device__ __forceinline__ void red_add_v4(float4* addr, float4 v) {
    asm volatile("red.global.add.v4.f32 [%0], {%1, %2, %3, %4};"
                 :: "l"(addr), "f"(v.x), "f"(v.y), "f"(v.z), "f"(v.w)
                 : "memory");
}
__device__ __forceinline__ void red_add_v2(float2* addr, float2 v) {
    asm volatile("red.global.add.v2.f32 [%0], {%1, %2};"
                 :: "l"(addr), "f"(v.x), "f"(v.y)
                 : "memory");
}
__device__ __forceinline__ float lrelu(float e) { return e > 0.f ? e : 0.2f * e; }

// ---------------- kernels ---------------------------------------------------
// init + dtype probe in one kernel.
__global__ void k_init(float* __restrict__ out, const void* edges) {
    int i = blockIdx.x * blockDim.x + threadIdx.x;
    if (i == 0) {
        const long long* p = (const long long*)edges;
        int ok = 1;
        for (int j = 0; j < 64; j++) {
            long long v = p[j];
            if (v < 0 || v >= NN) { ok = 0; break; }
        }
        g_is64 = ok;
    }
    if (i < NN) { g_s1[i] = make_float2(0.f, 0.f); g_s2[i] = 0.f; }
    if (i < NN * 32) g_out1[i] = 0.f;
    if (i < NN * 40) out[i] = 0.f;
}

// h1 = X @ W1 (128->32). 32 nodes/block, 128 threads.
// Thread = 4 nodes x 2 cols (c, c+16). (R10-identical compute)
__global__ void k_gemm1(const float* __restrict__ X, const float* __restrict__ W1,
                        const float* __restrict__ as1, const float* __restrict__ ad1) {
    __shared__ float Wt[32][132];       // [col][k], +4 pad
    __shared__ float Xs[32][128];       // [node][k]
    int t = threadIdx.x;
    for (int i = t; i < 4096; i += 128) {
        int k = i >> 5, c = i & 31;
        Wt[c][k] = W1[i];
    }
    int node0 = blockIdx.x * 32;
    {
        const float4* Xg = (const float4*)(X + (size_t)node0 * 128);
        float4* Xd = (float4*)&Xs[0][0];
        for (int i = t; i < 1024; i += 128) Xd[i] = Xg[i];
    }
    __syncthreads();

    int c = t & 15, g = t >> 4;
    const float4* wA = (const float4*)&Wt[c][0];
    const float4* wB = (const float4*)&Wt[c + 16][0];
    const float4* x0 = (const float4*)&Xs[g * 4 + 0][0];
    const float4* x1 = (const float4*)&Xs[g * 4 + 1][0];
    const float4* x2 = (const float4*)&Xs[g * 4 + 2][0];
    const float4* x3 = (const float4*)&Xs[g * 4 + 3][0];
    float accA[4] = {0.f, 0.f, 0.f, 0.f};
    float accB[4] = {0.f, 0.f, 0.f, 0.f};
#pragma unroll 4
    for (int kk = 0; kk < 32; kk++) {
        float4 wa = wA[kk], wb = wB[kk];
        float4 x;
        x = x0[kk];
        accA[0] = fmaf(x.x, wa.x, fmaf(x.y, wa.y, fmaf(x.z, wa.z, fmaf(x.w, wa.w, accA[0]))));
        accB[0] = fmaf(x.x, wb.x, fmaf(x.y, wb.y, fmaf(x.z, wb.z, fmaf(x.w, wb.w, accB[0]))));
        x = x1[kk];
        accA[1] = fmaf(x.x, wa.x, fmaf(x.y, wa.y, fmaf(x.z, wa.z, fmaf(x.w, wa.w, accA[1]))));
        accB[1] = fmaf(x.x, wb.x, fmaf(x.y, wb.y, fmaf(x.z, wb.z, fmaf(x.w, wb.w, accB[1]))));
        x = x2[kk];
        accA[2] = fmaf(x.x, wa.x, fmaf(x.y, wa.y, fmaf(x.z, wa.z, fmaf(x.w, wa.w, accA[2]))));
        accB[2] = fmaf(x.x, wb.x, fmaf(x.y, wb.y, fmaf(x.z, wb.z, fmaf(x.w, wb.w, accB[2]))));
        x = x3[kk];
        accA[3] = fmaf(x.x, wa.x, fmaf(x.y, wa.y, fmaf(x.z, wa.z, fmaf(x.w, wa.w, accA[3]))));
        accB[3] = fmaf(x.x, wb.x, fmaf(x.y, wb.y, fmaf(x.z, wb.z, fmaf(x.w, wb.w, accB[3]))));
    }

    float asA = as1[c], asB = as1[c + 16];
    float adA = ad1[c], adB = ad1[c + 16];
#pragma unroll
    for (int j = 0; j < 4; j++) {
        int node = node0 + g * 4 + j;
        g_h1[node * 32 + c]      = accA[j];
        g_h1[node * 32 + c + 16] = accB[j];
        float vs0 = accA[j] * asA;
        float vs1 = accB[j] * asB;
        float vd0 = accA[j] * adA;
        float vd1 = accB[j] * adB;
#pragma unroll
        for (int off = 8; off; off >>= 1) {
            vs0 += __shfl_xor_sync(0xffffffffu, vs0, off);
            vs1 += __shfl_xor_sync(0xffffffffu, vs1, off);
            vd0 += __shfl_xor_sync(0xffffffffu, vd0, off);
            vd1 += __shfl_xor_sync(0xffffffffu, vd1, off);
        }
        if (c == 0) g_a1[node] = make_float4(vs0, vs1, vd0, vd1);
    }
}

// ---- layer1: warp-cooperative fused edge pass. 8 lanes per 2 edges. ----
__global__ void k_msg1(const void* edges) {
    int gidx = blockIdx.x * blockDim.x + threadIdx.x;
    int grp = gidx >> 3, q = gidx & 7;
    int i0 = grp * 2;
    if (i0 >= ET) return;
    int s0, d0, s1, d1;
    if (i0 < EE) {     // EE even, i0 even -> pair never straddles boundary
        if (g_is64) {
            const longlong2* ps = (const longlong2*)edges;
            const longlong2* pd = (const longlong2*)((const long long*)edges + EE);
            longlong2 a = __ldg(ps + (i0 >> 1));
            longlong2 b = __ldg(pd + (i0 >> 1));
            s0 = (int)a.x; s1 = (int)a.y; d0 = (int)b.x; d1 = (int)b.y;
        } else {
            const int2* ps = (const int2*)edges;
            const int2* pd = (const int2*)((const int*)edges + EE);
            int2 a = __ldg(ps + (i0 >> 1));
            int2 b = __ldg(pd + (i0 >> 1));
            s0 = a.x; s1 = a.y; d0 = b.x; d1 = b.y;
        }
    } else {
        s0 = d0 = i0 - EE; s1 = d1 = i0 + 1 - EE;
    }
    if (q == 0) *((int4*)(g_edge + i0)) = make_int4(s0, d0, s1, d1);

    float4 as0 = __ldg(&g_a1[s0]);   // .x,.y = src coeffs
    float4 ad0 = __ldg(&g_a1[d0]);   // .z,.w = dst coeffs
    float4 as1v = __ldg(&g_a1[s1]);
    float4 ad1v = __ldg(&g_a1[d1]);
    float e00 = __expf(lrelu(as0.x + ad0.z));
    float e01 = __expf(lrelu(as0.y + ad0.w));
    float e10 = __expf(lrelu(as1v.x + ad1v.z));
    float e11 = __expf(lrelu(as1v.y + ad1v.w));
    if (q == 0) {
        red_add_v2(&g_s1[d0], make_float2(e00, e01));
        red_add_v2(&g_s1[d1], make_float2(e10, e11));
    }

    float4 v0 = __ldg((const float4*)(g_h1 + s0 * 32) + q);
    float4 v1 = __ldg((const float4*)(g_h1 + s1 * 32) + q);
    float a0 = (q < 4) ? e00 : e01;
    float a1 = (q < 4) ? e10 : e11;
    v0.x *= a0; v0.y *= a0; v0.z *= a0; v0.w *= a0;
    v1.x *= a1; v1.y *= a1; v1.z *= a1; v1.w *= a1;
    red_add_v4((float4*)(g_out1 + d0 * 32) + q, v0);
    red_add_v4((float4*)(g_out1 + d1 * 32) + q, v1);
}

// h2 = relu(out1/s1 + b1) @ W2 (32->40), fused normalization + a2 dot-products.
// 8 nodes / 320 threads.
__global__ void k_gemm2(const float* __restrict__ W2, const float* __restrict__ b1,
                        const float* __restrict__ as2, const float* __restrict__ ad2) {
    __shared__ float Ws[32 * 40];
    __shared__ float Xs[8][32];
    __shared__ float sA[8], sD[8];
    int t = threadIdx.x;
    if (t < 8) { sA[t] = 0.f; sD[t] = 0.f; }
    for (int i = t; i < 32 * 40; i += 320) Ws[i] = W2[i];
    int node0 = blockIdx.x * 8;
    for (int i = t; i < 8 * 32; i += 320) {
        int r = i >> 5, c = i & 31;
        float2 s = g_s1[node0 + r];
        float sv = (c < 16) ? s.x : s.y;
        float v = g_out1[(node0 + r) * 32 + c] / (sv + 1e-16f) + b1[c];
        Xs[r][c] = v > 0.f ? v : 0.f;
    }
    __syncthreads();
    int local = t / 40, col = t % 40;
    int node = node0 + local;
    float sum = 0.f;
#pragma unroll
    for (int k = 0; k < 32; k++) sum = fmaf(Xs[local][k], Ws[k * 40 + col], sum);
    g_h2[node * 40 + col] = sum;
    atomicAdd(&sA[local], sum * as2[col]);
    atomicAdd(&sD[local], sum * ad2[col]);
    __syncthreads();
    if (t < 8) g_a2[node0 + t] = make_float2(sA[t], sD[t]);
}

// ---- layer2: warp-cooperative fused edge pass into d_out. 8 lanes per 2 edges. ----
__global__ void k_msg2(float* __restrict__ out) {
    int gidx = blockIdx.x * blockDim.x + threadIdx.x;
    int grp = gidx >> 3, q = gidx & 7;
    int i0 = grp * 2;
    if (i0 >= ET) return;
    int4 e4 = __ldg((const int4*)(g_edge + i0));
    int s0 = e4.x, d0 = e4.y, s1 = e4.z, d1 = e4.w;

    float ex0 = __expf(lrelu(__ldg(&g_a2[s0]).x + __ldg(&g_a2[d0]).y));
    float ex1 = __expf(lrelu(__ldg(&g_a2[s1]).x + __ldg(&g_a2[d1]).y));
    if (q == 0) {
        atomicAdd(&g_s2[d0], ex0);
        atomicAdd(&g_s2[d1], ex1);
    }

    const float4* hp0 = (const float4*)(g_h2 + s0 * 40);
    const float4* hp1 = (const float4*)(g_h2 + s1 * 40);
    float4* op0 = (float4*)(out + d0 * 40);
    float4* op1 = (float4*)(out + d1 * 40);
    float4 v0 = __ldg(hp0 + q);
    float4 v1 = __ldg(hp1 + q);
    v0.x *= ex0; v0.y *= ex0; v0.z *= ex0; v0.w *= ex0;
    v1.x *= ex1; v1.y *= ex1; v1.z *= ex1; v1.w *= ex1;
    red_add_v4(op0 + q, v0);
    red_add_v4(op1 + q, v1);
    if (q < 2) {
        float4 w0 = __ldg(hp0 + 8 + q);
        float4 w1 = __ldg(hp1 + 8 + q);
        w0.x *= ex0; w0.y *= ex0; w0.z *= ex0; w0.w *= ex0;
        w1.x *= ex1; w1.y *= ex1; w1.z *= ex1; w1.w *= ex1;
        red_add_v4(op0 + 8 + q, w0);
        red_add_v4(op1 + 8 + q, w1);
    }
}

// Final: normalize by s2 and add bias.
__global__ void k_fin(float* __restrict__ out, const float* __restrict__ b2) {
    int i = blockIdx.x * blockDim.x + threadIdx.x;
    if (i >= NN * 40) return;
    int n = i / 40, c = i - n * 40;
    out[i] = out[i] / (g_s2[n] + 1e-16f) + b2[c];
}

// ---------------- launch ----------------------------------------------------
extern "C" void kernel_launch(void* const* d_in, const int* in_sizes, int n_in,
                              void* d_out, int out_size) {
    const float* X   = (const float*)d_in[0];
    const void*  edges = d_in[1];
    const float* W1  = (const float*)d_in[3];
    const float* as1 = (const float*)d_in[4];
    const float* ad1 = (const float*)d_in[5];
    const float* b1  = (const float*)d_in[6];
    const float* W2  = (const float*)d_in[7];
    const float* as2 = (const float*)d_in[8];
    const float* ad2 = (const float*)d_in[9];
    const float* b2  = (const float*)d_in[10];
    float* out = (float*)d_out;

    const long long TH = (long long)(ET / 2) * 8;      // 8 lanes per 2 edges
    const int EGW = (int)((TH + 255) / 256);

    k_init<<<(NN * 40 + 255) / 256, 256>>>(out, edges);
    k_gemm1<<<NN / 32, 128>>>(X, W1, as1, ad1);
    k_msg1<<<EGW, 256>>>(edges);
    k_gemm2<<<(NN + 7) / 8, 320>>>(W2, b1, as2, ad2);
    k_msg2<<<EGW, 256>>>(out);
    k_fin<<<(NN * 40 + 255) / 256, 256>>>(out, b2);
}

// round 16
// speedup vs baseline: 1.9020x; 1.9020x over previous
#include <cuda_runtime.h>

#define NN 100000
#define EE 3200000
#define ET (EE + NN)

// ---------------- scratch (device globals; no runtime allocation) ----------
__device__ int g_is64;
__device__ __align__(16) int2   g_edge[ET];        // decoded (src,dst) incl self-loops
__device__ __align__(16) float  g_h1[NN * 32];     // layer1 transformed features
__device__ __align__(8)  float2 g_a1s[NN];         // (a_src h0, a_src h1)
__device__ __align__(8)  float2 g_a1d[NN];         // (a_dst h0, a_dst h1)
__device__ __align__(8)  float2 g_s1[NN];          // segment expsum per head
__device__ __align__(16) float  g_out1[NN * 32];   // layer1 aggregate (unnormalized)
__device__ __align__(16) float  g_h2[NN * 40];
__device__ float g_a2s[NN];
__device__ float g_a2d[NN];
__device__ float g_s2[NN];

// ---------------- helpers ---------------------------------------------------
__device__ __forceinline__ void red_add_v4(float4* addr, float4 v) {
    asm volatile("red.global.add.v4.f32 [%0], {%1, %2, %3, %4};"
                 :: "l"(addr), "f"(v.x), "f"(v.y), "f"(v.z), "f"(v.w)
                 : "memory");
}
__device__ __forceinline__ void red_add_v2(float2* addr, float2 v) {
    asm volatile("red.global.add.v2.f32 [%0], {%1, %2};"
                 :: "l"(addr), "f"(v.x), "f"(v.y)
                 : "memory");
}
__device__ __forceinline__ float lrelu(float e) { return e > 0.f ? e : 0.2f * e; }

// ---------------- kernels ---------------------------------------------------
// init + dtype probe in one kernel.
__global__ void k_init(float* __restrict__ out, const void* edges) {
    int i = blockIdx.x * blockDim.x + threadIdx.x;
    if (i == 0) {
        const long long* p = (const long long*)edges;
        int ok = 1;
        for (int j = 0; j < 64; j++) {
            long long v = p[j];
            if (v < 0 || v >= NN) { ok = 0; break; }
        }
        g_is64 = ok;
    }
    if (i < NN) { g_s1[i] = make_float2(0.f, 0.f); g_s2[i] = 0.f; }
    if (i < NN * 32) g_out1[i] = 0.f;
    if (i < NN * 40) out[i] = 0.f;
}

// h1 = X @ W1 (128->32). 32 nodes/block, 128 threads.
// Thread = 4 nodes x 2 cols (c, c+16). (R10-identical)
__global__ void k_gemm1(const float* __restrict__ X, const float* __restrict__ W1,
                        const float* __restrict__ as1, const float* __restrict__ ad1) {
    __shared__ float Wt[32][132];       // [col][k], +4 pad
    __shared__ float Xs[32][128];       // [node][k]
    int t = threadIdx.x;
    for (int i = t; i < 4096; i += 128) {
        int k = i >> 5, c = i & 31;
        Wt[c][k] = W1[i];
    }
    int node0 = blockIdx.x * 32;
    {
        const float4* Xg = (const float4*)(X + (size_t)node0 * 128);
        float4* Xd = (float4*)&Xs[0][0];
        for (int i = t; i < 1024; i += 128) Xd[i] = Xg[i];
    }
    __syncthreads();

    int c = t & 15, g = t >> 4;
    const float4* wA = (const float4*)&Wt[c][0];
    const float4* wB = (const float4*)&Wt[c + 16][0];
    const float4* x0 = (const float4*)&Xs[g * 4 + 0][0];
    const float4* x1 = (const float4*)&Xs[g * 4 + 1][0];
    const float4* x2 = (const float4*)&Xs[g * 4 + 2][0];
    const float4* x3 = (const float4*)&Xs[g * 4 + 3][0];
    float accA[4] = {0.f, 0.f, 0.f, 0.f};
    float accB[4] = {0.f, 0.f, 0.f, 0.f};
#pragma unroll 4
    for (int kk = 0; kk < 32; kk++) {
        float4 wa = wA[kk], wb = wB[kk];
        float4 x;
        x = x0[kk];
        accA[0] = fmaf(x.x, wa.x, fmaf(x.y, wa.y, fmaf(x.z, wa.z, fmaf(x.w, wa.w, accA[0]))));
        accB[0] = fmaf(x.x, wb.x, fmaf(x.y, wb.y, fmaf(x.z, wb.z, fmaf(x.w, wb.w, accB[0]))));
        x = x1[kk];
        accA[1] = fmaf(x.x, wa.x, fmaf(x.y, wa.y, fmaf(x.z, wa.z, fmaf(x.w, wa.w, accA[1]))));
        accB[1] = fmaf(x.x, wb.x, fmaf(x.y, wb.y, fmaf(x.z, wb.z, fmaf(x.w, wb.w, accB[1]))));
        x = x2[kk];
        accA[2] = fmaf(x.x, wa.x, fmaf(x.y, wa.y, fmaf(x.z, wa.z, fmaf(x.w, wa.w, accA[2]))));
        accB[2] = fmaf(x.x, wb.x, fmaf(x.y, wb.y, fmaf(x.z, wb.z, fmaf(x.w, wb.w, accB[2]))));
        x = x3[kk];
        accA[3] = fmaf(x.x, wa.x, fmaf(x.y, wa.y, fmaf(x.z, wa.z, fmaf(x.w, wa.w, accA[3]))));
        accB[3] = fmaf(x.x, wb.x, fmaf(x.y, wb.y, fmaf(x.z, wb.z, fmaf(x.w, wb.w, accB[3]))));
    }

    float asA = as1[c], asB = as1[c + 16];
    float adA = ad1[c], adB = ad1[c + 16];
#pragma unroll
    for (int j = 0; j < 4; j++) {
        int node = node0 + g * 4 + j;
        g_h1[node * 32 + c]      = accA[j];
        g_h1[node * 32 + c + 16] = accB[j];
        float vs0 = accA[j] * asA;
        float vs1 = accB[j] * asB;
        float vd0 = accA[j] * adA;
        float vd1 = accB[j] * adB;
#pragma unroll
        for (int off = 8; off; off >>= 1) {
            vs0 += __shfl_xor_sync(0xffffffffu, vs0, off);
            vs1 += __shfl_xor_sync(0xffffffffu, vs1, off);
            vd0 += __shfl_xor_sync(0xffffffffu, vd0, off);
            vd1 += __shfl_xor_sync(0xffffffffu, vd1, off);
        }
        if (c == 0) {
            g_a1s[node] = make_float2(vs0, vs1);
            g_a1d[node] = make_float2(vd0, vd1);
        }
    }
}

// ---- layer1: warp-cooperative fused edge pass. 8 lanes per 2 edges. (R10-identical)
__global__ void k_msg1(const void* edges) {
    int gidx = blockIdx.x * blockDim.x + threadIdx.x;
    int grp = gidx >> 3, q = gidx & 7;
    int i0 = grp * 2;
    if (i0 >= ET) return;
    int s0, d0, s1, d1;
    if (i0 < EE) {     // EE even, i0 even -> pair never straddles boundary
        if (g_is64) {
            const longlong2* ps = (const longlong2*)edges;
            const longlong2* pd = (const longlong2*)((const long long*)edges + EE);
            longlong2 a = __ldg(ps + (i0 >> 1));
            longlong2 b = __ldg(pd + (i0 >> 1));
            s0 = (int)a.x; s1 = (int)a.y; d0 = (int)b.x; d1 = (int)b.y;
        } else {
            const int2* ps = (const int2*)edges;
            const int2* pd = (const int2*)((const int*)edges + EE);
            int2 a = __ldg(ps + (i0 >> 1));
            int2 b = __ldg(pd + (i0 >> 1));
            s0 = a.x; s1 = a.y; d0 = b.x; d1 = b.y;
        }
    } else {
        s0 = d0 = i0 - EE; s1 = d1 = i0 + 1 - EE;
    }
    if (q == 0) *((int4*)(g_edge + i0)) = make_int4(s0, d0, s1, d1);

    float2 as0 = __ldg(&g_a1s[s0]);
    float2 ad0 = __ldg(&g_a1d[d0]);
    float2 as1v = __ldg(&g_a1s[s1]);
    float2 ad1v = __ldg(&g_a1d[d1]);
    float e00 = __expf(lrelu(as0.x + ad0.x));
    float e01 = __expf(lrelu(as0.y + ad0.y));
    float e10 = __expf(lrelu(as1v.x + ad1v.x));
    float e11 = __expf(lrelu(as1v.y + ad1v.y));
    if (q == 0) {
        red_add_v2(&g_s1[d0], make_float2(e00, e01));
        red_add_v2(&g_s1[d1], make_float2(e10, e11));
    }

    float4 v0 = __ldg((const float4*)(g_h1 + s0 * 32) + q);
    float4 v1 = __ldg((const float4*)(g_h1 + s1 * 32) + q);
    float a0 = (q < 4) ? e00 : e01;
    float a1 = (q < 4) ? e10 : e11;
    v0.x *= a0; v0.y *= a0; v0.z *= a0; v0.w *= a0;
    v1.x *= a1; v1.y *= a1; v1.z *= a1; v1.w *= a1;
    red_add_v4((float4*)(g_out1 + d0 * 32) + q, v0);
    red_add_v4((float4*)(g_out1 + d1 * 32) + q, v1);
}

// h2 = relu(out1/s1 + b1) @ W2 (32->40), fused normalization + a2 dot-products
// via contention-free smem array + serial per-node reduction. 8 nodes / 320 thr.
__global__ void k_gemm2(const float* __restrict__ W2, const float* __restrict__ b1,
                        const float* __restrict__ as2, const float* __restrict__ ad2) {
    __shared__ float Ws[32 * 40];
    __shared__ float Xs[8][32];
    __shared__ float pA[320], pD[320];   // per-thread partials (no atomics)
    int t = threadIdx.x;
    for (int i = t; i < 32 * 40; i += 320) Ws[i] = W2[i];
    int node0 = blockIdx.x * 8;
    for (int i = t; i < 8 * 32; i += 320) {
        int r = i >> 5, c = i & 31;
        float2 s = g_s1[node0 + r];
        float sv = (c < 16) ? s.x : s.y;
        float v = g_out1[(node0 + r) * 32 + c] / (sv + 1e-16f) + b1[c];
        Xs[r][c] = v > 0.f ? v : 0.f;
    }
    __syncthreads();
    int local = t / 40, col = t % 40;
    int node = node0 + local;
    float sum = 0.f;
#pragma unroll
    for (int k = 0; k < 32; k++) sum = fmaf(Xs[local][k], Ws[k * 40 + col], sum);
    g_h2[node * 40 + col] = sum;
    pA[t] = sum * as2[col];
    pD[t] = sum * ad2[col];
    __syncthreads();
    if (t < 8) {
        float sa = 0.f, sd = 0.f;
        const float* a = pA + t * 40;
        const float* d = pD + t * 40;
#pragma unroll 8
        for (int k = 0; k < 40; k++) { sa += a[k]; sd += d[k]; }
        g_a2s[node0 + t] = sa;
        g_a2d[node0 + t] = sd;
    }
}

// ---- layer2: warp-cooperative fused edge pass into d_out. 8 lanes per 2 edges. ----
__global__ void k_msg2(float* __restrict__ out) {
    int gidx = blockIdx.x * blockDim.x + threadIdx.x;
    int grp = gidx >> 3, q = gidx & 7;
    int i0 = grp * 2;
    if (i0 >= ET) return;
    int4 e4 = __ldg((const int4*)(g_edge + i0));
    int s0 = e4.x, d0 = e4.y, s1 = e4.z, d1 = e4.w;

    float ex0 = __expf(lrelu(__ldg(&g_a2s[s0]) + __ldg(&g_a2d[d0])));
    float ex1 = __expf(lrelu(__ldg(&g_a2s[s1]) + __ldg(&g_a2d[d1])));
    if (q == 0) {
        atomicAdd(&g_s2[d0], ex0);
        atomicAdd(&g_s2[d1], ex1);
    }

    const float4* hp0 = (const float4*)(g_h2 + s0 * 40);
    const float4* hp1 = (const float4*)(g_h2 + s1 * 40);
    float4* op0 = (float4*)(out + d0 * 40);
    float4* op1 = (float4*)(out + d1 * 40);
    float4 v0 = __ldg(hp0 + q);
    float4 v1 = __ldg(hp1 + q);
    v0.x *= ex0; v0.y *= ex0; v0.z *= ex0; v0.w *= ex0;
    v1.x *= ex1; v1.y *= ex1; v1.z *= ex1; v1.w *= ex1;
    red_add_v4(op0 + q, v0);
    red_add_v4(op1 + q, v1);
    if (q < 2) {
        float4 w0 = __ldg(hp0 + 8 + q);
        float4 w1 = __ldg(hp1 + 8 + q);
        w0.x *= ex0; w0.y *= ex0; w0.z *= ex0; w0.w *= ex0;
        w1.x *= ex1; w1.y *= ex1; w1.z *= ex1; w1.w *= ex1;
        red_add_v4(op0 + 8 + q, w0);
        red_add_v4(op1 + 8 + q, w1);
    }
}

// Final: normalize by s2 and add bias.
__global__ void k_fin(float* __restrict__ out, const float* __restrict__ b2) {
    int i = blockIdx.x * blockDim.x + threadIdx.x;
    if (i >= NN * 40) return;
    int n = i / 40, c = i - n * 40;
    out[i] = out[i] / (g_s2[n] + 1e-16f) + b2[c];
}

// ---------------- launch ----------------------------------------------------
extern "C" void kernel_launch(void* const* d_in, const int* in_sizes, int n_in,
                              void* d_out, int out_size) {
    const float* X   = (const float*)d_in[0];
    const void*  edges = d_in[1];
    const float* W1  = (const float*)d_in[3];
    const float* as1 = (const float*)d_in[4];
    const float* ad1 = (const float*)d_in[5];
    const float* b1  = (const float*)d_in[6];
    const float* W2  = (const float*)d_in[7];
    const float* as2 = (const float*)d_in[8];
    const float* ad2 = (const float*)d_in[9];
    const float* b2  = (const float*)d_in[10];
    float* out = (float*)d_out;

    const long long TH = (long long)(ET / 2) * 8;      // 8 lanes per 2 edges
    const int EGW = (int)((TH + 255) / 256);

    k_init<<<(NN * 40 + 255) / 256, 256>>>(out, edges);
    k_gemm1<<<NN / 32, 128>>>(X, W1, as1, ad1);
    k_msg1<<<EGW, 256>>>(edges);
    k_gemm2<<<(NN + 7) / 8, 320>>>(W2, b1, as2, ad2);
    k_msg2<<<EGW, 256>>>(out);
    k_fin<<<(NN * 40 + 255) / 256, 256>>>(out, b2);
}